// round 15
// baseline (speedup 1.0000x reference)
#include <cuda_runtime.h>
#include <cuda_fp16.h>
#include <math.h>
#include <stdint.h>

#define DIMV 128

static const long V  = 50000;
static const long C  = 150000;
static const long EP = 200000;
static const long EN = 200000;
static const int  NITER = 4;
static const long NTOT = 2 * V + 2 * C;
static const long NSLOT = 2 * EP + 2 * EN;

// ---------------- scratch layout (4-byte units, all blocks 16B-aligned) ----------------
#define O_MSG_PV2C 0L
#define O_MSG_NV2C (O_MSG_PV2C + V*DIMV)
#define O_MSG_PC2V (O_MSG_NV2C + V*DIMV)
#define O_MSG_NC2V (O_MSG_PC2V + C*DIMV)
#define O_AGG_PV   (O_MSG_NC2V + C*DIMV)
#define O_AGG_NV   (O_AGG_PV + V*DIMV)
#define O_AGG_PC   (O_AGG_NV + V*DIMV)
#define O_AGG_NC   (O_AGG_PC + C*DIMV)
#define O_DEG      (O_AGG_NC + C*DIMV)
#define O_OFF      (O_DEG + NTOT)
#define O_CUR      (O_OFF + NTOT + 4)
#define O_CSRS     (O_CUR + NTOT)
#define O_CSRN     (O_CSRS + NSLOT)
#define O_PART     (O_CSRN + NSLOT)
#define O_WFRAG    (O_PART + 512)                // fp16 frag weights: 14 blocks x 8192 words
#define SCRATCH_TOTAL (O_WFRAG + 14L*8192)

__device__ float g_scratch[SCRATCH_TOTAL];

// ---------------- fp16 helpers ----------------

__device__ __forceinline__ uint32_t f2h2(float lo, float hi)
{
    uint32_t r;
    asm("cvt.rn.f16x2.f32 %0, %1, %2;" : "=r"(r) : "f"(hi), "f"(lo));
    return r;
}

__device__ __forceinline__ void mma_f16(float* c, const uint32_t* a, uint32_t b0, uint32_t b1)
{
    asm volatile("mma.sync.aligned.m16n8k16.row.col.f32.f16.f16.f32 "
                 "{%0,%1,%2,%3}, {%4,%5,%6,%7}, {%8,%9}, {%0,%1,%2,%3};"
                 : "+f"(c[0]), "+f"(c[1]), "+f"(c[2]), "+f"(c[3])
                 : "r"(a[0]), "r"(a[1]), "r"(a[2]), "r"(a[3]), "r"(b0), "r"(b1));
}

// One-time fp16 B-fragment permutation for all 14 weight blocks.
__global__ void wprep_kernel(const float* __restrict__ W1, const float* __restrict__ W2,
                             const float* __restrict__ cW, const float* __restrict__ vW,
                             uint16_t* __restrict__ dst)
{
    int blk = blockIdx.x;  // 0..13
    const float* src;
    if (blk < 4)       src = W1 + blk * 16384;
    else if (blk < 8)  src = W2 + (blk - 4) * 16384;
    else if (blk < 11) src = cW + (blk - 8) * 16384;
    else               src = vW + (blk - 11) * 16384;
    uint16_t* d = dst + (long)blk * 16384;
    for (int idx = threadIdx.x; idx < 16384; idx += blockDim.x) {
        int k = idx >> 7, n = idx & 127;
        int ks = k >> 4, kk = k & 15;
        int reg = kk >> 3, t = (kk & 7) >> 1, hw = kk & 1;
        int ntile = n >> 3, nn = n & 7;
        long pos = ((((long)(ks * 16 + ntile) * 32 + nn * 4 + t) * 2 + reg) * 2 + hw);
        __half h = __float2half_rn(src[idx]);
        d[pos] = __half_as_ushort(h);
    }
}

// ---------------- CSR build (one-time) ----------------

__global__ void zero_kernel(int* __restrict__ D, int n)
{
    for (int i = blockIdx.x * blockDim.x + threadIdx.x; i < n; i += gridDim.x * blockDim.x)
        D[i] = 0;
}

template<int PNEG>
__global__ void deg_kernel(const int* __restrict__ ev, const int* __restrict__ ec,
                           const int* __restrict__ sel, int nE, int* __restrict__ D)
{
    int e = blockIdx.x * blockDim.x + threadIdx.x;
    if (e >= nE) return;
    int ed = sel[e];
    atomicAdd(&D[(PNEG ? V : 0) + ev[ed]], 1);
    atomicAdd(&D[2 * V + (PNEG ? C : 0) + ec[ed]], 1);
}

#define SCHUNK 1024
#define SNB 391

__global__ void scansum_kernel(const int* __restrict__ D, int* __restrict__ P)
{
    __shared__ int sm[256];
    int b = blockIdx.x, t = threadIdx.x;
    int g0 = b * SCHUNK + t * 4;
    int s = 0;
    #pragma unroll
    for (int k = 0; k < 4; k++) {
        int i = g0 + k;
        if (i < NTOT) s += D[i];
    }
    sm[t] = s;
    __syncthreads();
    for (int o = 128; o > 0; o >>= 1) {
        if (t < o) sm[t] += sm[t + o];
        __syncthreads();
    }
    if (t == 0) P[b] = sm[0];
}

__global__ void scanmid_kernel(int* __restrict__ P)
{
    __shared__ int sm[512];
    int t = threadIdx.x;
    sm[t] = (t < SNB) ? P[t] : 0;
    __syncthreads();
    for (int o = 1; o < 512; o <<= 1) {
        int v = (t >= o) ? sm[t - o] : 0;
        __syncthreads();
        sm[t] += v;
        __syncthreads();
    }
    if (t < SNB) P[t] = (t == 0) ? 0 : sm[t - 1];
}

__global__ void scanout_kernel(const int* __restrict__ D, const int* __restrict__ P,
                               int* __restrict__ off, int* __restrict__ cur)
{
    __shared__ int sm[256];
    int b = blockIdx.x, t = threadIdx.x;
    int g0 = b * SCHUNK + t * 4;
    int d[4], s = 0;
    #pragma unroll
    for (int k = 0; k < 4; k++) {
        int i = g0 + k;
        d[k] = (i < NTOT) ? D[i] : 0;
        s += d[k];
    }
    sm[t] = s;
    __syncthreads();
    for (int o = 1; o < 256; o <<= 1) {
        int v = (t >= o) ? sm[t - o] : 0;
        __syncthreads();
        sm[t] += v;
        __syncthreads();
    }
    int run = P[b] + ((t == 0) ? 0 : sm[t - 1]);
    #pragma unroll
    for (int k = 0; k < 4; k++) {
        int i = g0 + k;
        if (i < NTOT) {
            off[i] = run;
            cur[i] = run;
            if (i == NTOT - 1) off[NTOT] = run + d[k];
            run += d[k];
        }
    }
}

template<int PNEG>
__global__ void place_kernel(const int* __restrict__ ev, const int* __restrict__ ec,
                             const int* __restrict__ sel, int nE,
                             const int* __restrict__ D, int* __restrict__ cur,
                             int* __restrict__ csrS, float* __restrict__ csrN)
{
    int e = blockIdx.x * blockDim.x + threadIdx.x;
    if (e >= nE) return;
    int ed = sel[e];
    int v = ev[ed], c = ec[ed];
    long iv = (PNEG ? V : 0) + v;
    long ic = 2 * V + (PNEG ? C : 0) + c;
    int dv = max(D[iv], 1), dc = max(D[ic], 1);
    float ninv = rsqrtf((float)(dv * dc));
    int sv = atomicAdd(&cur[iv], 1);
    csrS[sv] = c; csrN[sv] = ninv;
    int sc = atomicAdd(&cur[ic], 1);
    csrS[sc] = v; csrN[sc] = ninv;
}

// ---------------- aggregation: one warp per dest node ----------------
__global__ void agg_kernel(const int* __restrict__ off, const int* __restrict__ csrS,
                           const float* __restrict__ csrN,
                           const float* __restrict__ msgPC2V, const float* __restrict__ msgNC2V,
                           const float* __restrict__ msgPV2C, const float* __restrict__ msgNV2C,
                           float* __restrict__ aggPV, float* __restrict__ aggNV,
                           float* __restrict__ aggPC, float* __restrict__ aggNC)
{
    long wid = (long)(blockIdx.x * blockDim.x + threadIdx.x) >> 5;
    int lane = threadIdx.x & 31;
    if (wid >= NTOT) return;

    const float* msg;
    float* dst;
    if (wid < V)               { msg = msgPC2V; dst = aggPV + wid * DIMV; }
    else if (wid < 2 * V)      { msg = msgNC2V; dst = aggNV + (wid - V) * DIMV; }
    else if (wid < 2 * V + C)  { msg = msgPV2C; dst = aggPC + (wid - 2 * V) * DIMV; }
    else                       { msg = msgNV2C; dst = aggNC + (wid - 2 * V - C) * DIMV; }

    int j0 = off[wid], j1 = off[wid + 1];
    float4 acc = make_float4(0.f, 0.f, 0.f, 0.f);
    for (int j = j0; j < j1; j++) {
        int s = csrS[j];
        float wn = csrN[j];
        float4 m = ((const float4*)(msg + (long)s * DIMV))[lane];
        acc.x += wn * m.x; acc.y += wn * m.y;
        acc.z += wn * m.z; acc.w += wn * m.w;
    }
    ((float4*)dst)[lane] = acc;
}

// ---------------- fp16 GEMM machinery ----------------
#define APITCH 68

// acc[2][4][4] += As(32-row strip at wr) @ Bs(32-col strip at wc), K=128 (8 ks)
__device__ __forceinline__ void mma_block32(float acc[2][4][4],
                                            const uint32_t* __restrict__ As,
                                            const uint32_t* __restrict__ Bs,
                                            int wr, int wc, int lane, int q, int t)
{
    #pragma unroll
    for (int ks = 0; ks < 8; ks++) {
        uint32_t a[2][4];
        #pragma unroll
        for (int mi = 0; mi < 2; mi++) {
            const uint32_t* Ap = As + (wr * 32 + mi * 16 + q) * APITCH + ks * 8 + t;
            a[mi][0] = Ap[0];
            a[mi][1] = Ap[8 * APITCH];
            a[mi][2] = Ap[4];
            a[mi][3] = Ap[8 * APITCH + 4];
        }
        #pragma unroll
        for (int ni = 0; ni < 4; ni++) {
            uint2 b = ((const uint2*)Bs)[(ks * 16 + wc * 4 + ni) * 32 + lane];
            mma_f16(acc[0][ni], a[0], b.x, b.y);
            mma_f16(acc[1][ni], a[1], b.x, b.y);
        }
    }
}

// ---------------- fused 2-layer MLP (fp16, 256 thr, 64-row tiles, 2 CTA/SM) ----------------
// smem words: Bs1[0..8192) Bs2[8192..16384) As[16384..16384+64*68)
#define MLP_SMEM ((16384 + 64 * APITCH) * 4)
#define GGRID 296

__global__ __launch_bounds__(256, 2)
void mlp_fused_kernel(const float* __restrict__ X,
                      const uint32_t* __restrict__ Wf1, const uint32_t* __restrict__ Wf2,
                      const float* __restrict__ b1, const float* __restrict__ b2,
                      float* __restrict__ out, int N)
{
    extern __shared__ uint32_t sm[];
    uint32_t* Bs1 = sm;
    uint32_t* Bs2 = sm + 8192;
    uint32_t* As  = sm + 16384;

    const int tid = threadIdx.x;
    const int w = tid >> 5, lane = tid & 31;
    const int wr = w >> 2, wc = w & 3;
    const int q = lane >> 2, t = lane & 3;

    {
        const uint4* s1 = (const uint4*)Wf1;
        const uint4* s2 = (const uint4*)Wf2;
        uint4* d1 = (uint4*)Bs1;
        uint4* d2 = (uint4*)Bs2;
        #pragma unroll
        for (int i = 0; i < 8; i++) {
            d1[tid + i * 256] = s1[tid + i * 256];
            d2[tid + i * 256] = s2[tid + i * 256];
        }
    }
    float2 bv1[4], bv2[4];
    #pragma unroll
    for (int ni = 0; ni < 4; ni++) {
        bv1[ni] = *(const float2*)(b1 + wc * 32 + ni * 8 + t * 2);
        bv2[ni] = *(const float2*)(b2 + wc * 32 + ni * 8 + t * 2);
    }

    const float4* Xg = (const float4*)X;
    const int xr = tid >> 5, xc4 = tid & 31;   // rows xr+8i, i<8
    float4 xreg[8];

    const int ntiles = (N + 63) >> 6;
    long tile = blockIdx.x;
    if (tile < ntiles) {
        const long row0 = tile << 6;
        #pragma unroll
        for (int i = 0; i < 8; i++) {
            long rr = row0 + xr + i * 8;
            xreg[i] = (rr < N) ? Xg[rr * 32 + xc4] : make_float4(0.f, 0.f, 0.f, 0.f);
        }
    }
    __syncthreads();

    for (; tile < ntiles; tile += gridDim.x) {
        const long row0 = tile << 6;

        // regs -> As (fp16x2, pitch 68)
        #pragma unroll
        for (int i = 0; i < 8; i++) {
            uint2 u;
            u.x = f2h2(xreg[i].x, xreg[i].y);
            u.y = f2h2(xreg[i].z, xreg[i].w);
            *(uint2*)(As + (xr + i * 8) * APITCH + xc4 * 2) = u;
        }
        __syncthreads();

        // layer 1
        float acc[2][4][4] = {};
        mma_block32(acc, As, Bs1, wr, wc, lane, q, t);
        __syncthreads();

        // relu(acc + b1) -> As (fp16x2)
        #pragma unroll
        for (int mi = 0; mi < 2; mi++)
            #pragma unroll
            for (int h = 0; h < 2; h++) {
                int r = wr * 32 + mi * 16 + h * 8 + q;
                #pragma unroll
                for (int ni = 0; ni < 4; ni++) {
                    float o0 = fmaxf(acc[mi][ni][h * 2 + 0] + bv1[ni].x, 0.f);
                    float o1 = fmaxf(acc[mi][ni][h * 2 + 1] + bv1[ni].y, 0.f);
                    As[r * APITCH + wc * 16 + ni * 4 + t] = f2h2(o0, o1);
                }
            }
        __syncthreads();

        // prefetch next tile (hidden behind layer-2 mma)
        const long ntile = tile + gridDim.x;
        if (ntile < ntiles) {
            const long nrow0 = ntile << 6;
            #pragma unroll
            for (int i = 0; i < 8; i++) {
                long rr = nrow0 + xr + i * 8;
                xreg[i] = (rr < N) ? Xg[rr * 32 + xc4] : make_float4(0.f, 0.f, 0.f, 0.f);
            }
        }

        // layer 2
        float acc2[2][4][4] = {};
        mma_block32(acc2, As, Bs2, wr, wc, lane, q, t);

        // store msg (fp32)
        #pragma unroll
        for (int mi = 0; mi < 2; mi++)
            #pragma unroll
            for (int h = 0; h < 2; h++) {
                long rg = row0 + wr * 32 + mi * 16 + h * 8 + q;
                if (rg < N) {
                    #pragma unroll
                    for (int ni = 0; ni < 4; ni++) {
                        int col = wc * 32 + ni * 8 + t * 2;
                        float o0 = acc2[mi][ni][h * 2 + 0] + bv2[ni].x;
                        float o1 = acc2[mi][ni][h * 2 + 1] + bv2[ni].y;
                        *(float2*)(out + rg * DIMV + col) = make_float2(o0, o1);
                    }
                }
            }
        __syncthreads();
    }
}

// ---------------- fused K=384 update (fp16, 256 thr, 64-row tiles, 2 CTA/SM) ----------------
// smem words: Bs 3*8192, As 64*68  -> 115,712 B/CTA
#define UPD_SMEM ((24576 + 64 * APITCH) * 4)

__global__ __launch_bounds__(256, 2)
void upd_fused_kernel(const float* __restrict__ X0, const float* __restrict__ X1,
                      const float* __restrict__ X2,
                      const uint32_t* __restrict__ Wf,
                      const float* __restrict__ bias,
                      float* __restrict__ out, int N)
{
    extern __shared__ uint32_t sm[];
    uint32_t* Bs = sm;
    uint32_t* As = sm + 24576;

    const int tid = threadIdx.x;
    const int w = tid >> 5, lane = tid & 31;
    const int wr = w >> 2, wc = w & 3;
    const int q = lane >> 2, t = lane & 3;

    {
        const uint4* src = (const uint4*)Wf;
        uint4* dst = (uint4*)Bs;
        #pragma unroll
        for (int i = 0; i < 24; i++) dst[tid + i * 256] = src[tid + i * 256];
    }
    float2 bv[4];
    #pragma unroll
    for (int ni = 0; ni < 4; ni++)
        bv[ni] = *(const float2*)(bias + wc * 32 + ni * 8 + t * 2);

    const float* Xs[3] = {X0, X1, X2};
    const int xr = tid >> 5, xc4 = tid & 31;   // rows xr+8i, i<8
    float4 xreg[8];

    const int ntiles = (N + 63) >> 6;
    long tile = blockIdx.x;
    if (tile < ntiles) {
        const long row0 = tile << 6;
        const float4* Xg = (const float4*)X0;
        #pragma unroll
        for (int i = 0; i < 8; i++) {
            long rr = row0 + xr + i * 8;
            xreg[i] = (rr < N) ? Xg[rr * 32 + xc4] : make_float4(0.f, 0.f, 0.f, 0.f);
        }
    }
    __syncthreads();

    for (; tile < ntiles; tile += gridDim.x) {
        const long row0 = tile << 6;

        float acc[2][4][4] = {};
        #pragma unroll
        for (int p = 0; p < 3; p++) {
            #pragma unroll
            for (int i = 0; i < 8; i++) {
                uint2 u;
                u.x = f2h2(xreg[i].x, xreg[i].y);
                u.y = f2h2(xreg[i].z, xreg[i].w);
                *(uint2*)(As + (xr + i * 8) * APITCH + xc4 * 2) = u;
            }
            __syncthreads();

            if (p < 2) {
                const float4* Xg = (const float4*)Xs[p + 1];
                #pragma unroll
                for (int i = 0; i < 8; i++) {
                    long rr = row0 + xr + i * 8;
                    xreg[i] = (rr < N) ? Xg[rr * 32 + xc4] : make_float4(0.f, 0.f, 0.f, 0.f);
                }
            } else {
                const long ntile = tile + gridDim.x;
                if (ntile < ntiles) {
                    const long nrow0 = ntile << 6;
                    const float4* Xg = (const float4*)X0;
                    #pragma unroll
                    for (int i = 0; i < 8; i++) {
                        long rr = nrow0 + xr + i * 8;
                        xreg[i] = (rr < N) ? Xg[rr * 32 + xc4] : make_float4(0.f, 0.f, 0.f, 0.f);
                    }
                }
            }

            mma_block32(acc, As, Bs + p * 8192, wr, wc, lane, q, t);
            __syncthreads();
        }

        #pragma unroll
        for (int mi = 0; mi < 2; mi++)
            #pragma unroll
            for (int h = 0; h < 2; h++) {
                long rg = row0 + wr * 32 + mi * 16 + h * 8 + q;
                if (rg < N) {
                    #pragma unroll
                    for (int ni = 0; ni < 4; ni++) {
                        int col = wc * 32 + ni * 8 + t * 2;
                        float o0 = acc[mi][ni][h * 2 + 0] + bv[ni].x;
                        float o1 = acc[mi][ni][h * 2 + 1] + bv[ni].y;
                        *(float2*)(out + rg * DIMV + col) = make_float2(o0, o1);
                    }
                }
            }
    }
}

// ---------------- host side ----------------

extern "C" void kernel_launch(void* const* d_in, const int* in_sizes, int n_in,
                              void* d_out, int out_size)
{
    const int ofs = n_in - 14;
    const int*   v_edge = (const int*)d_in[ofs + 0];
    const int*   c_edge = (const int*)d_in[ofs + 1];
    const int*   p_sel  = (const int*)d_in[ofs + 2];
    const int*   n_sel  = (const int*)d_in[ofs + 3];
    const float* v_emb0 = (const float*)d_in[ofs + 4];
    const float* c_emb0 = (const float*)d_in[ofs + 5];
    const float* W1     = (const float*)d_in[ofs + 6];
    const float* b1     = (const float*)d_in[ofs + 7];
    const float* W2     = (const float*)d_in[ofs + 8];
    const float* b2     = (const float*)d_in[ofs + 9];
    const float* cW     = (const float*)d_in[ofs + 10];
    const float* cB     = (const float*)d_in[ofs + 11];
    const float* vW     = (const float*)d_in[ofs + 12];
    const float* vB     = (const float*)d_in[ofs + 13];

    float* base = nullptr;
    cudaGetSymbolAddress((void**)&base, g_scratch);

    float* msgPV2C = base + O_MSG_PV2C;
    float* msgNV2C = base + O_MSG_NV2C;
    float* msgPC2V = base + O_MSG_PC2V;
    float* msgNC2V = base + O_MSG_NC2V;
    float* aggPV   = base + O_AGG_PV;
    float* aggNV   = base + O_AGG_NV;
    float* aggPC   = base + O_AGG_PC;
    float* aggNC   = base + O_AGG_NC;
    int*   D       = (int*)(base + O_DEG);
    int*   off     = (int*)(base + O_OFF);
    int*   cur     = (int*)(base + O_CUR);
    int*   csrS    = (int*)(base + O_CSRS);
    float* csrN    = base + O_CSRN;
    int*   P       = (int*)(base + O_PART);
    uint32_t* wf   = (uint32_t*)(base + O_WFRAG);

    float* out = (float*)d_out;
    float* OV = out;                    // [5][V][128]
    float* OC = out + 5L * V * DIMV;    // [5][C][128]

    cudaFuncSetAttribute(mlp_fused_kernel, cudaFuncAttributeMaxDynamicSharedMemorySize, MLP_SMEM);
    cudaFuncSetAttribute(upd_fused_kernel, cudaFuncAttributeMaxDynamicSharedMemorySize, UPD_SMEM);

    // one-time prep (launch #4 overall = first C-sized MLP for ncu)
    wprep_kernel<<<14, 256>>>(W1, W2, cW, vW, (uint16_t*)wf);
    zero_kernel<<<200, 256>>>(D, (int)NTOT);
    deg_kernel<0><<<(unsigned)((EP + 255) / 256), 256>>>(v_edge, c_edge, p_sel, (int)EP, D);

    for (int it = 0; it < NITER; it++) {
        const float* Vc = (it == 0) ? v_emb0 : OV + (long)it * V * DIMV;
        const float* Cc = (it == 0) ? c_emb0 : OC + (long)it * C * DIMV;
        float* Vn = OV + (long)(it + 1) * V * DIMV;
        float* Cn = OC + (long)(it + 1) * C * DIMV;

        // 4 fused 2-layer MLPs (fp16 mma, 2 CTA/SM)
        mlp_fused_kernel<<<GGRID, 256, MLP_SMEM>>>(Cc, wf + 2L * 8192, wf + 6L * 8192,
                                                   b1 + 2 * 128, b2 + 2 * 128, msgPC2V, (int)C);
        mlp_fused_kernel<<<GGRID, 256, MLP_SMEM>>>(Cc, wf + 3L * 8192, wf + 7L * 8192,
                                                   b1 + 3 * 128, b2 + 3 * 128, msgNC2V, (int)C);
        mlp_fused_kernel<<<GGRID, 256, MLP_SMEM>>>(Vc, wf + 0L * 8192, wf + 4L * 8192,
                                                   b1 + 0 * 128, b2 + 0 * 128, msgPV2C, (int)V);
        mlp_fused_kernel<<<GGRID, 256, MLP_SMEM>>>(Vc, wf + 1L * 8192, wf + 5L * 8192,
                                                   b1 + 1 * 128, b2 + 1 * 128, msgNV2C, (int)V);

        if (it == 0) {
            deg_kernel<1><<<(unsigned)((EN + 255) / 256), 256>>>(v_edge, c_edge, n_sel, (int)EN, D);
            scansum_kernel<<<SNB, 256>>>(D, P);
            scanmid_kernel<<<1, 512>>>(P);
            scanout_kernel<<<SNB, 256>>>(D, P, off, cur);
            place_kernel<0><<<(unsigned)((EP + 255) / 256), 256>>>(v_edge, c_edge, p_sel, (int)EP, D, cur, csrS, csrN);
            place_kernel<1><<<(unsigned)((EN + 255) / 256), 256>>>(v_edge, c_edge, n_sel, (int)EN, D, cur, csrS, csrN);
        }

        // CSR aggregation (fp32)
        agg_kernel<<<(unsigned)((NTOT * 32 + 255) / 256), 256>>>(off, csrS, csrN,
                                                                 msgPC2V, msgNC2V, msgPV2C, msgNV2C,
                                                                 aggPV, aggNV, aggPC, aggNC);

        // fused K=384 updates (fp16 mma, 2 CTA/SM)
        upd_fused_kernel<<<GGRID, 256, UPD_SMEM>>>(Cc, aggPC, aggNC, wf + 8L * 8192, cB, Cn, (int)C);
        upd_fused_kernel<<<GGRID, 256, UPD_SMEM>>>(Vc, aggPV, aggNV, wf + 11L * 8192, vB, Vn, (int)V);
    }

    cudaMemcpyAsync(OV, v_emb0, V * DIMV * sizeof(float), cudaMemcpyDeviceToDevice);
    cudaMemcpyAsync(OC, c_emb0, C * DIMV * sizeof(float), cudaMemcpyDeviceToDevice);
}

// round 16
// speedup vs baseline: 1.0922x; 1.0922x over previous
#include <cuda_runtime.h>
#include <cuda_fp16.h>
#include <math.h>
#include <stdint.h>

#define DIMV 128

static const long V  = 50000;
static const long C  = 150000;
static const long EP = 200000;
static const long EN = 200000;
static const int  NITER = 4;
static const long NTOT = 2 * V + 2 * C;
static const long NSLOT = 2 * EP + 2 * EN;

// ---------------- scratch layout (4-byte units, all blocks 16B-aligned) ----------------
// msg/agg buffers are fp16: 64 words per row of 128.
#define O_MSG_PV2C 0L
#define O_MSG_NV2C (O_MSG_PV2C + V*64)
#define O_MSG_PC2V (O_MSG_NV2C + V*64)
#define O_MSG_NC2V (O_MSG_PC2V + C*64)
#define O_AGG_PV   (O_MSG_NC2V + C*64)
#define O_AGG_NV   (O_AGG_PV + V*64)
#define O_AGG_PC   (O_AGG_NV + V*64)
#define O_AGG_NC   (O_AGG_PC + C*64)
#define O_DEG      (O_AGG_NC + C*64)
#define O_OFF      (O_DEG + NTOT)
#define O_CUR      (O_OFF + NTOT + 4)
#define O_CSRS     (O_CUR + NTOT)
#define O_CSRN     (O_CSRS + NSLOT)
#define O_PART     (O_CSRN + NSLOT)
#define O_WFRAG    (O_PART + 512)                // fp16 frag weights: 14 blocks x 8192 words
#define SCRATCH_TOTAL (O_WFRAG + 14L*8192)

__device__ float g_scratch[SCRATCH_TOTAL];

// ---------------- fp16 helpers ----------------

__device__ __forceinline__ uint32_t f2h2(float lo, float hi)
{
    uint32_t r;
    asm("cvt.rn.f16x2.f32 %0, %1, %2;" : "=r"(r) : "f"(hi), "f"(lo));
    return r;
}

__device__ __forceinline__ void mma_f16(float* c, const uint32_t* a, uint32_t b0, uint32_t b1)
{
    asm volatile("mma.sync.aligned.m16n8k16.row.col.f32.f16.f16.f32 "
                 "{%0,%1,%2,%3}, {%4,%5,%6,%7}, {%8,%9}, {%0,%1,%2,%3};"
                 : "+f"(c[0]), "+f"(c[1]), "+f"(c[2]), "+f"(c[3])
                 : "r"(a[0]), "r"(a[1]), "r"(a[2]), "r"(a[3]), "r"(b0), "r"(b1));
}

// One-time fp16 B-fragment permutation for all 14 weight blocks.
__global__ void wprep_kernel(const float* __restrict__ W1, const float* __restrict__ W2,
                             const float* __restrict__ cW, const float* __restrict__ vW,
                             uint16_t* __restrict__ dst)
{
    int blk = blockIdx.x;  // 0..13
    const float* src;
    if (blk < 4)       src = W1 + blk * 16384;
    else if (blk < 8)  src = W2 + (blk - 4) * 16384;
    else if (blk < 11) src = cW + (blk - 8) * 16384;
    else               src = vW + (blk - 11) * 16384;
    uint16_t* d = dst + (long)blk * 16384;
    for (int idx = threadIdx.x; idx < 16384; idx += blockDim.x) {
        int k = idx >> 7, n = idx & 127;
        int ks = k >> 4, kk = k & 15;
        int reg = kk >> 3, t = (kk & 7) >> 1, hw = kk & 1;
        int ntile = n >> 3, nn = n & 7;
        long pos = ((((long)(ks * 16 + ntile) * 32 + nn * 4 + t) * 2 + reg) * 2 + hw);
        __half h = __float2half_rn(src[idx]);
        d[pos] = __half_as_ushort(h);
    }
}

// ---------------- CSR build (one-time) ----------------

__global__ void zero_kernel(int* __restrict__ D, int n)
{
    for (int i = blockIdx.x * blockDim.x + threadIdx.x; i < n; i += gridDim.x * blockDim.x)
        D[i] = 0;
}

template<int PNEG>
__global__ void deg_kernel(const int* __restrict__ ev, const int* __restrict__ ec,
                           const int* __restrict__ sel, int nE, int* __restrict__ D)
{
    int e = blockIdx.x * blockDim.x + threadIdx.x;
    if (e >= nE) return;
    int ed = sel[e];
    atomicAdd(&D[(PNEG ? V : 0) + ev[ed]], 1);
    atomicAdd(&D[2 * V + (PNEG ? C : 0) + ec[ed]], 1);
}

#define SCHUNK 1024
#define SNB 391

__global__ void scansum_kernel(const int* __restrict__ D, int* __restrict__ P)
{
    __shared__ int sm[256];
    int b = blockIdx.x, t = threadIdx.x;
    int g0 = b * SCHUNK + t * 4;
    int s = 0;
    #pragma unroll
    for (int k = 0; k < 4; k++) {
        int i = g0 + k;
        if (i < NTOT) s += D[i];
    }
    sm[t] = s;
    __syncthreads();
    for (int o = 128; o > 0; o >>= 1) {
        if (t < o) sm[t] += sm[t + o];
        __syncthreads();
    }
    if (t == 0) P[b] = sm[0];
}

__global__ void scanmid_kernel(int* __restrict__ P)
{
    __shared__ int sm[512];
    int t = threadIdx.x;
    sm[t] = (t < SNB) ? P[t] : 0;
    __syncthreads();
    for (int o = 1; o < 512; o <<= 1) {
        int v = (t >= o) ? sm[t - o] : 0;
        __syncthreads();
        sm[t] += v;
        __syncthreads();
    }
    if (t < SNB) P[t] = (t == 0) ? 0 : sm[t - 1];
}

__global__ void scanout_kernel(const int* __restrict__ D, const int* __restrict__ P,
                               int* __restrict__ off, int* __restrict__ cur)
{
    __shared__ int sm[256];
    int b = blockIdx.x, t = threadIdx.x;
    int g0 = b * SCHUNK + t * 4;
    int d[4], s = 0;
    #pragma unroll
    for (int k = 0; k < 4; k++) {
        int i = g0 + k;
        d[k] = (i < NTOT) ? D[i] : 0;
        s += d[k];
    }
    sm[t] = s;
    __syncthreads();
    for (int o = 1; o < 256; o <<= 1) {
        int v = (t >= o) ? sm[t - o] : 0;
        __syncthreads();
        sm[t] += v;
        __syncthreads();
    }
    int run = P[b] + ((t == 0) ? 0 : sm[t - 1]);
    #pragma unroll
    for (int k = 0; k < 4; k++) {
        int i = g0 + k;
        if (i < NTOT) {
            off[i] = run;
            cur[i] = run;
            if (i == NTOT - 1) off[NTOT] = run + d[k];
            run += d[k];
        }
    }
}

template<int PNEG>
__global__ void place_kernel(const int* __restrict__ ev, const int* __restrict__ ec,
                             const int* __restrict__ sel, int nE,
                             const int* __restrict__ D, int* __restrict__ cur,
                             int* __restrict__ csrS, float* __restrict__ csrN)
{
    int e = blockIdx.x * blockDim.x + threadIdx.x;
    if (e >= nE) return;
    int ed = sel[e];
    int v = ev[ed], c = ec[ed];
    long iv = (PNEG ? V : 0) + v;
    long ic = 2 * V + (PNEG ? C : 0) + c;
    int dv = max(D[iv], 1), dc = max(D[ic], 1);
    float ninv = rsqrtf((float)(dv * dc));
    int sv = atomicAdd(&cur[iv], 1);
    csrS[sv] = c; csrN[sv] = ninv;
    int sc = atomicAdd(&cur[ic], 1);
    csrS[sc] = v; csrN[sc] = ninv;
}

// ---------------- aggregation: one warp per dest node (fp16 msg -> fp16 agg) ----------------
__global__ void agg_kernel(const int* __restrict__ off, const int* __restrict__ csrS,
                           const float* __restrict__ csrN,
                           const uint32_t* __restrict__ msgPC2V, const uint32_t* __restrict__ msgNC2V,
                           const uint32_t* __restrict__ msgPV2C, const uint32_t* __restrict__ msgNV2C,
                           uint32_t* __restrict__ aggPV, uint32_t* __restrict__ aggNV,
                           uint32_t* __restrict__ aggPC, uint32_t* __restrict__ aggNC)
{
    long wid = (long)(blockIdx.x * blockDim.x + threadIdx.x) >> 5;
    int lane = threadIdx.x & 31;
    if (wid >= NTOT) return;

    const uint32_t* msg;
    uint32_t* dst;
    if (wid < V)               { msg = msgPC2V; dst = aggPV + wid * 64; }
    else if (wid < 2 * V)      { msg = msgNC2V; dst = aggNV + (wid - V) * 64; }
    else if (wid < 2 * V + C)  { msg = msgPV2C; dst = aggPC + (wid - 2 * V) * 64; }
    else                       { msg = msgNV2C; dst = aggNC + (wid - 2 * V - C) * 64; }

    int j0 = off[wid], j1 = off[wid + 1];
    float4 acc = make_float4(0.f, 0.f, 0.f, 0.f);
    for (int j = j0; j < j1; j++) {
        int s = csrS[j];
        float wn = csrN[j];
        uint2 m = ((const uint2*)msg)[(long)s * 32 + lane];   // 4 halves
        float2 f0 = __half22float2(*(__half2*)&m.x);
        float2 f1 = __half22float2(*(__half2*)&m.y);
        acc.x += wn * f0.x; acc.y += wn * f0.y;
        acc.z += wn * f1.x; acc.w += wn * f1.y;
    }
    uint2 o;
    o.x = f2h2(acc.x, acc.y);
    o.y = f2h2(acc.z, acc.w);
    ((uint2*)dst)[lane] = o;
}

// ---------------- fp16 GEMM machinery ----------------
#define APITCH 68

__device__ __forceinline__ void mma_block32(float acc[2][4][4],
                                            const uint32_t* __restrict__ As,
                                            const uint32_t* __restrict__ Bs,
                                            int wr, int wc, int lane, int q, int t)
{
    #pragma unroll
    for (int ks = 0; ks < 8; ks++) {
        uint32_t a[2][4];
        #pragma unroll
        for (int mi = 0; mi < 2; mi++) {
            const uint32_t* Ap = As + (wr * 32 + mi * 16 + q) * APITCH + ks * 8 + t;
            a[mi][0] = Ap[0];
            a[mi][1] = Ap[8 * APITCH];
            a[mi][2] = Ap[4];
            a[mi][3] = Ap[8 * APITCH + 4];
        }
        #pragma unroll
        for (int ni = 0; ni < 4; ni++) {
            uint2 b = ((const uint2*)Bs)[(ks * 16 + wc * 4 + ni) * 32 + lane];
            mma_f16(acc[0][ni], a[0], b.x, b.y);
            mma_f16(acc[1][ni], a[1], b.x, b.y);
        }
    }
}

// ---------------- fused 2-layer MLP (fp16, 256 thr, 64-row tiles, 2 CTA/SM) ----------------
#define MLP_SMEM ((16384 + 64 * APITCH) * 4)
#define GGRID 296

__global__ __launch_bounds__(256, 2)
void mlp_fused_kernel(const float* __restrict__ X,
                      const uint32_t* __restrict__ Wf1, const uint32_t* __restrict__ Wf2,
                      const float* __restrict__ b1, const float* __restrict__ b2,
                      uint32_t* __restrict__ outh, int N)   // fp16x2 output
{
    extern __shared__ uint32_t sm[];
    uint32_t* Bs1 = sm;
    uint32_t* Bs2 = sm + 8192;
    uint32_t* As  = sm + 16384;

    const int tid = threadIdx.x;
    const int w = tid >> 5, lane = tid & 31;
    const int wr = w >> 2, wc = w & 3;
    const int q = lane >> 2, t = lane & 3;

    {
        const uint4* s1 = (const uint4*)Wf1;
        const uint4* s2 = (const uint4*)Wf2;
        uint4* d1 = (uint4*)Bs1;
        uint4* d2 = (uint4*)Bs2;
        #pragma unroll
        for (int i = 0; i < 8; i++) {
            d1[tid + i * 256] = s1[tid + i * 256];
            d2[tid + i * 256] = s2[tid + i * 256];
        }
    }
    float2 bv1[4], bv2[4];
    #pragma unroll
    for (int ni = 0; ni < 4; ni++) {
        bv1[ni] = *(const float2*)(b1 + wc * 32 + ni * 8 + t * 2);
        bv2[ni] = *(const float2*)(b2 + wc * 32 + ni * 8 + t * 2);
    }

    const float4* Xg = (const float4*)X;
    const int xr = tid >> 5, xc4 = tid & 31;   // rows xr+8i, i<8
    float4 xreg[8];

    const int ntiles = (N + 63) >> 6;
    long tile = blockIdx.x;
    if (tile < ntiles) {
        const long row0 = tile << 6;
        #pragma unroll
        for (int i = 0; i < 8; i++) {
            long rr = row0 + xr + i * 8;
            xreg[i] = (rr < N) ? Xg[rr * 32 + xc4] : make_float4(0.f, 0.f, 0.f, 0.f);
        }
    }
    __syncthreads();

    for (; tile < ntiles; tile += gridDim.x) {
        const long row0 = tile << 6;

        #pragma unroll
        for (int i = 0; i < 8; i++) {
            uint2 u;
            u.x = f2h2(xreg[i].x, xreg[i].y);
            u.y = f2h2(xreg[i].z, xreg[i].w);
            *(uint2*)(As + (xr + i * 8) * APITCH + xc4 * 2) = u;
        }
        __syncthreads();

        // layer 1
        float acc[2][4][4] = {};
        mma_block32(acc, As, Bs1, wr, wc, lane, q, t);
        __syncthreads();

        // relu(acc + b1) -> As (fp16x2)
        #pragma unroll
        for (int mi = 0; mi < 2; mi++)
            #pragma unroll
            for (int h = 0; h < 2; h++) {
                int r = wr * 32 + mi * 16 + h * 8 + q;
                #pragma unroll
                for (int ni = 0; ni < 4; ni++) {
                    float o0 = fmaxf(acc[mi][ni][h * 2 + 0] + bv1[ni].x, 0.f);
                    float o1 = fmaxf(acc[mi][ni][h * 2 + 1] + bv1[ni].y, 0.f);
                    As[r * APITCH + wc * 16 + ni * 4 + t] = f2h2(o0, o1);
                }
            }
        __syncthreads();

        // prefetch next tile (hidden behind layer-2 mma)
        const long ntile = tile + gridDim.x;
        if (ntile < ntiles) {
            const long nrow0 = ntile << 6;
            #pragma unroll
            for (int i = 0; i < 8; i++) {
                long rr = nrow0 + xr + i * 8;
                xreg[i] = (rr < N) ? Xg[rr * 32 + xc4] : make_float4(0.f, 0.f, 0.f, 0.f);
            }
        }

        // layer 2
        float acc2[2][4][4] = {};
        mma_block32(acc2, As, Bs2, wr, wc, lane, q, t);

        // store msg as fp16x2
        #pragma unroll
        for (int mi = 0; mi < 2; mi++)
            #pragma unroll
            for (int h = 0; h < 2; h++) {
                long rg = row0 + wr * 32 + mi * 16 + h * 8 + q;
                if (rg < N) {
                    #pragma unroll
                    for (int ni = 0; ni < 4; ni++) {
                        int col = wc * 32 + ni * 8 + t * 2;
                        float o0 = acc2[mi][ni][h * 2 + 0] + bv2[ni].x;
                        float o1 = acc2[mi][ni][h * 2 + 1] + bv2[ni].y;
                        outh[rg * 64 + (col >> 1)] = f2h2(o0, o1);
                    }
                }
            }
        __syncthreads();
    }
}

// ---------------- fused K=384 update (X0 fp32, X1/X2 fp16 agg; 2 CTA/SM) ----------------
#define UPD_SMEM ((24576 + 64 * APITCH) * 4)

__global__ __launch_bounds__(256, 2)
void upd_fused_kernel(const float* __restrict__ X0,
                      const uint32_t* __restrict__ X1h, const uint32_t* __restrict__ X2h,
                      const uint32_t* __restrict__ Wf,
                      const float* __restrict__ bias,
                      float* __restrict__ out, int N)
{
    extern __shared__ uint32_t sm[];
    uint32_t* Bs = sm;
    uint32_t* As = sm + 24576;

    const int tid = threadIdx.x;
    const int w = tid >> 5, lane = tid & 31;
    const int wr = w >> 2, wc = w & 3;
    const int q = lane >> 2, t = lane & 3;

    {
        const uint4* src = (const uint4*)Wf;
        uint4* dst = (uint4*)Bs;
        #pragma unroll
        for (int i = 0; i < 24; i++) dst[tid + i * 256] = src[tid + i * 256];
    }
    float2 bv[4];
    #pragma unroll
    for (int ni = 0; ni < 4; ni++)
        bv[ni] = *(const float2*)(bias + wc * 32 + ni * 8 + t * 2);

    const int xr = tid >> 5, xc4 = tid & 31;   // rows xr+8i, i<8
    uint2 hreg[8];

    const int ntiles = (N + 63) >> 6;
    long tile = blockIdx.x;
    if (tile < ntiles) {
        const long row0 = tile << 6;
        const float4* Xg = (const float4*)X0;
        #pragma unroll
        for (int i = 0; i < 8; i++) {
            long rr = row0 + xr + i * 8;
            float4 v = (rr < N) ? Xg[rr * 32 + xc4] : make_float4(0.f, 0.f, 0.f, 0.f);
            hreg[i].x = f2h2(v.x, v.y);
            hreg[i].y = f2h2(v.z, v.w);
        }
    }
    __syncthreads();

    for (; tile < ntiles; tile += gridDim.x) {
        const long row0 = tile << 6;

        float acc[2][4][4] = {};
        #pragma unroll
        for (int p = 0; p < 3; p++) {
            #pragma unroll
            for (int i = 0; i < 8; i++)
                *(uint2*)(As + (xr + i * 8) * APITCH + xc4 * 2) = hreg[i];
            __syncthreads();

            // prefetch next phase / next tile (hidden behind mma)
            if (p < 2) {
                const uint2* Xh = (const uint2*)(p == 0 ? X1h : X2h);
                #pragma unroll
                for (int i = 0; i < 8; i++) {
                    long rr = row0 + xr + i * 8;
                    hreg[i] = (rr < N) ? Xh[rr * 32 + xc4] : make_uint2(0u, 0u);
                }
            } else {
                const long ntile = tile + gridDim.x;
                if (ntile < ntiles) {
                    const long nrow0 = ntile << 6;
                    const float4* Xg = (const float4*)X0;
                    #pragma unroll
                    for (int i = 0; i < 8; i++) {
                        long rr = nrow0 + xr + i * 8;
                        float4 v = (rr < N) ? Xg[rr * 32 + xc4] : make_float4(0.f, 0.f, 0.f, 0.f);
                        hreg[i].x = f2h2(v.x, v.y);
                        hreg[i].y = f2h2(v.z, v.w);
                    }
                }
            }

            mma_block32(acc, As, Bs + p * 8192, wr, wc, lane, q, t);
            __syncthreads();
        }

        #pragma unroll
        for (int mi = 0; mi < 2; mi++)
            #pragma unroll
            for (int h = 0; h < 2; h++) {
                long rg = row0 + wr * 32 + mi * 16 + h * 8 + q;
                if (rg < N) {
                    #pragma unroll
                    for (int ni = 0; ni < 4; ni++) {
                        int col = wc * 32 + ni * 8 + t * 2;
                        float o0 = acc[mi][ni][h * 2 + 0] + bv[ni].x;
                        float o1 = acc[mi][ni][h * 2 + 1] + bv[ni].y;
                        *(float2*)(out + rg * DIMV + col) = make_float2(o0, o1);
                    }
                }
            }
    }
}

// ---------------- host side ----------------

extern "C" void kernel_launch(void* const* d_in, const int* in_sizes, int n_in,
                              void* d_out, int out_size)
{
    const int ofs = n_in - 14;
    const int*   v_edge = (const int*)d_in[ofs + 0];
    const int*   c_edge = (const int*)d_in[ofs + 1];
    const int*   p_sel  = (const int*)d_in[ofs + 2];
    const int*   n_sel  = (const int*)d_in[ofs + 3];
    const float* v_emb0 = (const float*)d_in[ofs + 4];
    const float* c_emb0 = (const float*)d_in[ofs + 5];
    const float* W1     = (const float*)d_in[ofs + 6];
    const float* b1     = (const float*)d_in[ofs + 7];
    const float* W2     = (const float*)d_in[ofs + 8];
    const float* b2     = (const float*)d_in[ofs + 9];
    const float* cW     = (const float*)d_in[ofs + 10];
    const float* cB     = (const float*)d_in[ofs + 11];
    const float* vW     = (const float*)d_in[ofs + 12];
    const float* vB     = (const float*)d_in[ofs + 13];

    float* base = nullptr;
    cudaGetSymbolAddress((void**)&base, g_scratch);

    uint32_t* msgPV2C = (uint32_t*)(base + O_MSG_PV2C);
    uint32_t* msgNV2C = (uint32_t*)(base + O_MSG_NV2C);
    uint32_t* msgPC2V = (uint32_t*)(base + O_MSG_PC2V);
    uint32_t* msgNC2V = (uint32_t*)(base + O_MSG_NC2V);
    uint32_t* aggPV   = (uint32_t*)(base + O_AGG_PV);
    uint32_t* aggNV   = (uint32_t*)(base + O_AGG_NV);
    uint32_t* aggPC   = (uint32_t*)(base + O_AGG_PC);
    uint32_t* aggNC   = (uint32_t*)(base + O_AGG_NC);
    int*   D       = (int*)(base + O_DEG);
    int*   off     = (int*)(base + O_OFF);
    int*   cur     = (int*)(base + O_CUR);
    int*   csrS    = (int*)(base + O_CSRS);
    float* csrN    = base + O_CSRN;
    int*   P       = (int*)(base + O_PART);
    uint32_t* wf   = (uint32_t*)(base + O_WFRAG);

    float* out = (float*)d_out;
    float* OV = out;                    // [5][V][128]
    float* OC = out + 5L * V * DIMV;    // [5][C][128]

    cudaFuncSetAttribute(mlp_fused_kernel, cudaFuncAttributeMaxDynamicSharedMemorySize, MLP_SMEM);
    cudaFuncSetAttribute(upd_fused_kernel, cudaFuncAttributeMaxDynamicSharedMemorySize, UPD_SMEM);

    // one-time prep (launch #4 overall = first C-sized MLP for ncu)
    wprep_kernel<<<14, 256>>>(W1, W2, cW, vW, (uint16_t*)wf);
    zero_kernel<<<200, 256>>>(D, (int)NTOT);
    deg_kernel<0><<<(unsigned)((EP + 255) / 256), 256>>>(v_edge, c_edge, p_sel, (int)EP, D);

    for (int it = 0; it < NITER; it++) {
        const float* Vc = (it == 0) ? v_emb0 : OV + (long)it * V * DIMV;
        const float* Cc = (it == 0) ? c_emb0 : OC + (long)it * C * DIMV;
        float* Vn = OV + (long)(it + 1) * V * DIMV;
        float* Cn = OC + (long)(it + 1) * C * DIMV;

        // 4 fused 2-layer MLPs (fp16 mma, fp16 msg out, 2 CTA/SM)
        mlp_fused_kernel<<<GGRID, 256, MLP_SMEM>>>(Cc, wf + 2L * 8192, wf + 6L * 8192,
                                                   b1 + 2 * 128, b2 + 2 * 128, msgPC2V, (int)C);
        mlp_fused_kernel<<<GGRID, 256, MLP_SMEM>>>(Cc, wf + 3L * 8192, wf + 7L * 8192,
                                                   b1 + 3 * 128, b2 + 3 * 128, msgNC2V, (int)C);
        mlp_fused_kernel<<<GGRID, 256, MLP_SMEM>>>(Vc, wf + 0L * 8192, wf + 4L * 8192,
                                                   b1 + 0 * 128, b2 + 0 * 128, msgPV2C, (int)V);
        mlp_fused_kernel<<<GGRID, 256, MLP_SMEM>>>(Vc, wf + 1L * 8192, wf + 5L * 8192,
                                                   b1 + 1 * 128, b2 + 1 * 128, msgNV2C, (int)V);

        if (it == 0) {
            deg_kernel<1><<<(unsigned)((EN + 255) / 256), 256>>>(v_edge, c_edge, n_sel, (int)EN, D);
            scansum_kernel<<<SNB, 256>>>(D, P);
            scanmid_kernel<<<1, 512>>>(P);
            scanout_kernel<<<SNB, 256>>>(D, P, off, cur);
            place_kernel<0><<<(unsigned)((EP + 255) / 256), 256>>>(v_edge, c_edge, p_sel, (int)EP, D, cur, csrS, csrN);
            place_kernel<1><<<(unsigned)((EN + 255) / 256), 256>>>(v_edge, c_edge, n_sel, (int)EN, D, cur, csrS, csrN);
        }

        // CSR aggregation (fp16 in/out, fp32 accumulate)
        agg_kernel<<<(unsigned)((NTOT * 32 + 255) / 256), 256>>>(off, csrS, csrN,
                                                                 msgPC2V, msgNC2V, msgPV2C, msgNV2C,
                                                                 aggPV, aggNV, aggPC, aggNC);

        // fused K=384 updates
        upd_fused_kernel<<<GGRID, 256, UPD_SMEM>>>(Cc, aggPC, aggNC, wf + 8L * 8192, cB, Cn, (int)C);
        upd_fused_kernel<<<GGRID, 256, UPD_SMEM>>>(Vc, aggPV, aggNV, wf + 11L * 8192, vB, Vn, (int)V);
    }

    cudaMemcpyAsync(OV, v_emb0, V * DIMV * sizeof(float), cudaMemcpyDeviceToDevice);
    cudaMemcpyAsync(OC, c_emb0, C * DIMV * sizeof(float), cudaMemcpyDeviceToDevice);
}